// round 1
// baseline (speedup 1.0000x reference)
#include <cuda_runtime.h>

// YOLO-v1 loss, shapes: pred/target (2048, 28, 28, 30) fp32 -> scalar fp32.
// Strategy: stage per-block contiguous chunks (128 cells x 30 ch) into smem via
// coalesced float4 loads; one thread per cell computes the loss contribution;
// warp+block reduce; one atomicAdd per block.

#define CELLS (2048 * 28 * 28)   // 1,605,632
#define CH    30
#define TPB   128
#define FLOATS_PER_BLK (TPB * CH)        // 3840 floats per tensor
#define VEC4_PER_BLK   (FLOATS_PER_BLK / 4)  // 960

#define LAMBDA_COORD 5.0f
#define LAMBDA_NOOBJ 0.5f

__global__ void zero_out_kernel(float* out) {
    out[0] = 0.0f;
}

__device__ __forceinline__ float sq(float x) { return x * x; }

__global__ __launch_bounds__(TPB) void yolo_loss_kernel(
    const float* __restrict__ pred,
    const float* __restrict__ tgt,
    float* __restrict__ out)
{
    __shared__ float sp[FLOATS_PER_BLK];
    __shared__ float st[FLOATS_PER_BLK];
    __shared__ float warp_sums[TPB / 32];

    const int tid  = threadIdx.x;
    const int base = blockIdx.x * FLOATS_PER_BLK;   // fits in int (< 48.2M)

    // Coalesced staging: 16B-aligned (FLOATS_PER_BLK*4 = 30720 % 16 == 0)
    const float4* gp = reinterpret_cast<const float4*>(pred + base);
    const float4* gt = reinterpret_cast<const float4*>(tgt + base);
    float4* s4p = reinterpret_cast<float4*>(sp);
    float4* s4t = reinterpret_cast<float4*>(st);

    #pragma unroll
    for (int i = tid; i < VEC4_PER_BLK; i += TPB) {
        s4p[i] = gp[i];
        s4t[i] = gt[i];
    }
    __syncthreads();

    const float* p = sp + tid * CH;
    const float* t = st + tid * CH;

    const float t0 = t[0], t1 = t[1], t2 = t[2], t3 = t[3], t4 = t[4];
    const float obj   = (t4 > 0.0f)  ? 1.0f : 0.0f;
    const float noobj = (t4 == 0.0f) ? 1.0f : 0.0f;

    // IoU of pred box 1 (ch 0..3) and box 2 (ch 5..8) vs target box (ch 0..3)
    const float tarea = (t2 - t0) * (t3 - t1);

    float iou1, iou2;
    {
        float lt0 = fmaxf(p[0], t0), lt1 = fmaxf(p[1], t1);
        float rb0 = fminf(p[2], t2), rb1 = fminf(p[3], t3);
        float w = fmaxf(rb0 - lt0, 0.0f), h = fmaxf(rb1 - lt1, 0.0f);
        float inter = w * h;
        float a1 = (p[2] - p[0]) * (p[3] - p[1]);
        iou1 = inter / (a1 + tarea - inter);
    }
    {
        float lt0 = fmaxf(p[5], t0), lt1 = fmaxf(p[6], t1);
        float rb0 = fminf(p[7], t2), rb1 = fminf(p[8], t3);
        float w = fmaxf(rb0 - lt0, 0.0f), h = fmaxf(rb1 - lt1, 0.0f);
        float inter = w * h;
        float a1 = (p[7] - p[5]) * (p[8] - p[6]);
        iou2 = inter / (a1 + tarea - inter);
    }

    // jnp.argmax picks first index on ties -> box 1 wins when iou1 >= iou2
    const float c0 = (iou1 >= iou2) ? 1.0f : 0.0f;
    const float c1 = 1.0f - c0;

    // loss1: xy coords
    float l1 = (sq(p[0] - t0) + sq(p[1] - t1)) * c0
             + (sq(p[5] - t[5]) + sq(p[6] - t[6])) * c1;

    // loss2: sqrt wh
    float l2 = (sq(sqrtf(p[2]) - sqrtf(t2)) + sq(sqrtf(p[3]) - sqrtf(t3))) * c0
             + (sq(sqrtf(p[7]) - sqrtf(t[7])) + sq(sqrtf(p[8]) - sqrtf(t[8]))) * c1;

    // conf losses (loss3 obj-weighted, loss4 noobj-weighted — same box-gated expr)
    float conf = sq(p[4] - t4) * c0 + sq(p[9] - t[9]) * c1;

    // loss5: class channels 10..29
    float l5 = 0.0f;
    #pragma unroll
    for (int k = 10; k < CH; ++k)
        l5 += sq(p[k] - t[k]);

    float cell = obj * (LAMBDA_COORD * (l1 + l2) + conf + l5)
               + LAMBDA_NOOBJ * noobj * conf;

    // Warp reduce
    #pragma unroll
    for (int o = 16; o > 0; o >>= 1)
        cell += __shfl_xor_sync(0xFFFFFFFFu, cell, o);

    if ((tid & 31) == 0) warp_sums[tid >> 5] = cell;
    __syncthreads();

    if (tid == 0) {
        float s = warp_sums[0] + warp_sums[1] + warp_sums[2] + warp_sums[3];
        atomicAdd(out, s);
    }
}

extern "C" void kernel_launch(void* const* d_in, const int* in_sizes, int n_in,
                              void* d_out, int out_size)
{
    const float* pred = (const float*)d_in[0];
    const float* tgt  = (const float*)d_in[1];
    float* out = (float*)d_out;

    zero_out_kernel<<<1, 1>>>(out);
    yolo_loss_kernel<<<CELLS / TPB, TPB>>>(pred, tgt, out);
}

// round 2
// speedup vs baseline: 1.1832x; 1.1832x over previous
#include <cuda_runtime.h>
#include <cstdint>

// YOLO-v1 loss: pred/target (2048, 28, 28, 30) fp32 -> scalar fp32.
// Persistent blocks + 3-stage cp.async pipeline into smem; thread-per-cell
// compute from smem; per-thread accumulator across chunks; one atomic/block.

#define CELLS   (2048 * 28 * 28)        // 1,605,632
#define CH      30
#define TPB     128
#define CPC     128                     // cells per chunk
#define NCHUNK  (CELLS / CPC)           // 12,544
#define GRID_B  296                     // 2 blocks per SM on 148 SMs
#define STAGES  3

#define CHUNK_FLOATS   (CPC * CH)       // 3840 floats per tensor per chunk
#define STAGE_FLOATS   (2 * CHUNK_FLOATS)  // 7680 (pred then tgt)
#define STAGE_BYTES    (STAGE_FLOATS * 4)  // 30720
#define VEC4_PER_STAGE (STAGE_FLOATS / 4)  // 1920
#define V4_ITERS       (VEC4_PER_STAGE / TPB) // 15

#define LAMBDA_COORD 5.0f
#define LAMBDA_NOOBJ 0.5f

__global__ void zero_out_kernel(float* out) { out[0] = 0.0f; }

__device__ __forceinline__ float sq(float x) { return x * x; }

__device__ __forceinline__ void issue_chunk(
    const float* __restrict__ pred, const float* __restrict__ tgt,
    float* stage, int chunk, int tid)
{
    if (chunk < NCHUNK) {
        const char* pb = (const char*)(pred + (size_t)chunk * CHUNK_FLOATS);
        const char* tb = (const char*)(tgt  + (size_t)chunk * CHUNK_FLOATS);
        uint32_t sb = (uint32_t)__cvta_generic_to_shared(stage);
        #pragma unroll
        for (int k = 0; k < V4_ITERS; ++k) {
            int i = tid + k * TPB;                      // 0..1919
            const char* src = (i < CHUNK_FLOATS / 4) ? (pb + (size_t)i * 16)
                                                     : (tb + (size_t)(i - CHUNK_FLOATS / 4) * 16);
            asm volatile("cp.async.cg.shared.global [%0], [%1], 16;\n"
                         :: "r"(sb + i * 16), "l"(src));
        }
    }
    asm volatile("cp.async.commit_group;\n");
}

__device__ __forceinline__ float cell_loss(const float* stage, int tid)
{
    const float* p = stage + tid * CH;
    const float* t = stage + CHUNK_FLOATS + tid * CH;

    const float t0 = t[0], t1 = t[1], t2 = t[2], t3 = t[3], t4 = t[4];
    const float obj   = (t4 > 0.0f)  ? 1.0f : 0.0f;
    const float noobj = (t4 == 0.0f) ? 1.0f : 0.0f;
    const float tarea = (t2 - t0) * (t3 - t1);

    float iou1, iou2;
    {
        float lt0 = fmaxf(p[0], t0), lt1 = fmaxf(p[1], t1);
        float rb0 = fminf(p[2], t2), rb1 = fminf(p[3], t3);
        float w = fmaxf(rb0 - lt0, 0.0f), h = fmaxf(rb1 - lt1, 0.0f);
        float inter = w * h;
        float a1 = (p[2] - p[0]) * (p[3] - p[1]);
        iou1 = inter / (a1 + tarea - inter);
    }
    {
        float lt0 = fmaxf(p[5], t0), lt1 = fmaxf(p[6], t1);
        float rb0 = fminf(p[7], t2), rb1 = fminf(p[8], t3);
        float w = fmaxf(rb0 - lt0, 0.0f), h = fmaxf(rb1 - lt1, 0.0f);
        float inter = w * h;
        float a1 = (p[7] - p[5]) * (p[8] - p[6]);
        iou2 = inter / (a1 + tarea - inter);
    }

    // jnp.argmax tie -> first index: box 1 wins when iou1 >= iou2
    const float c0 = (iou1 >= iou2) ? 1.0f : 0.0f;
    const float c1 = 1.0f - c0;

    float l1 = (sq(p[0] - t0) + sq(p[1] - t1)) * c0
             + (sq(p[5] - t[5]) + sq(p[6] - t[6])) * c1;

    float l2 = (sq(sqrtf(p[2]) - sqrtf(t2)) + sq(sqrtf(p[3]) - sqrtf(t3))) * c0
             + (sq(sqrtf(p[7]) - sqrtf(t[7])) + sq(sqrtf(p[8]) - sqrtf(t[8]))) * c1;

    float conf = sq(p[4] - t4) * c0 + sq(p[9] - t[9]) * c1;

    float l5 = 0.0f;
    #pragma unroll
    for (int k = 10; k < CH; ++k)
        l5 += sq(p[k] - t[k]);

    return obj * (LAMBDA_COORD * (l1 + l2) + conf + l5)
         + LAMBDA_NOOBJ * noobj * conf;
}

extern __shared__ float smem[];   // STAGES * STAGE_FLOATS

__global__ __launch_bounds__(TPB) void yolo_loss_kernel(
    const float* __restrict__ pred,
    const float* __restrict__ tgt,
    float* __restrict__ out)
{
    const int tid = threadIdx.x;
    const int bid = blockIdx.x;

    // Prologue: fill the pipeline
    #pragma unroll
    for (int s = 0; s < STAGES; ++s)
        issue_chunk(pred, tgt, smem + s * STAGE_FLOATS, bid + s * GRID_B, tid);

    float acc = 0.0f;
    int stage_idx = 0;

    for (int c = bid; c < NCHUNK; c += GRID_B) {
        // Wait until the oldest group (this stage) has landed
        asm volatile("cp.async.wait_group %0;\n" :: "n"(STAGES - 1));
        __syncthreads();

        float* stage = smem + stage_idx * STAGE_FLOATS;
        acc += cell_loss(stage, tid);

        __syncthreads();   // everyone done reading this stage before refill
        issue_chunk(pred, tgt, stage, c + STAGES * GRID_B, tid);

        stage_idx = (stage_idx + 1 == STAGES) ? 0 : stage_idx + 1;
    }

    // Drain remaining (possibly empty) groups so smem reuse below is safe
    asm volatile("cp.async.wait_group 0;\n");
    __syncthreads();

    // Final reduction: warp shuffle -> smem -> single atomic per block
    #pragma unroll
    for (int o = 16; o > 0; o >>= 1)
        acc += __shfl_xor_sync(0xFFFFFFFFu, acc, o);

    if ((tid & 31) == 0) smem[tid >> 5] = acc;
    __syncthreads();

    if (tid == 0) {
        float s = smem[0] + smem[1] + smem[2] + smem[3];
        atomicAdd(out, s);
    }
}

extern "C" void kernel_launch(void* const* d_in, const int* in_sizes, int n_in,
                              void* d_out, int out_size)
{
    const float* pred = (const float*)d_in[0];
    const float* tgt  = (const float*)d_in[1];
    float* out = (float*)d_out;

    static bool attr_set = false;
    if (!attr_set) {
        cudaFuncSetAttribute(yolo_loss_kernel,
                             cudaFuncAttributeMaxDynamicSharedMemorySize,
                             STAGES * STAGE_BYTES);
        attr_set = true;
    }

    zero_out_kernel<<<1, 1>>>(out);
    yolo_loss_kernel<<<GRID_B, TPB, STAGES * STAGE_BYTES>>>(pred, tgt, out);
}